// round 1
// baseline (speedup 1.0000x reference)
#include <cuda_runtime.h>

// CovarianceLayer: x [64, 4, 8192, 16] fp32 -> cov [64, 4, 16, 16] fp32
// cov[b,c] = (X - mean)^T (X - mean) / (T-1), variables = M=16, observations = T=8192.
// Single pass per (b,c): accumulate S_mn = sum x_m x_n (upper triangle, 136) and
// s_m = sum x_m (16), then cov = (S - s_m s_n / T) / (T - 1).

#define T_DIM   8192
#define M_DIM   16
#define NTHREADS 256
#define NPAIRS  136   // 16*17/2
#define NACC    152   // 136 products + 16 sums

__device__ __forceinline__ int tri_idx(int m, int n) {
    // m <= n
    return m * (31 - m) / 2 + n;
}

__global__ void __launch_bounds__(NTHREADS, 1)
cov_kernel(const float* __restrict__ x, float* __restrict__ out)
{
    const int bc  = blockIdx.x;            // 0..255 -> (b,c) pair
    const int tid = threadIdx.x;

    const float4* __restrict__ xp =
        reinterpret_cast<const float4*>(x + (size_t)bc * T_DIM * M_DIM);
    // row t occupies float4s [t*4, t*4+4)

    float acc[NACC];
    #pragma unroll
    for (int i = 0; i < NACC; i++) acc[i] = 0.0f;

    // Each thread handles rows tid, tid+256, ... ; unroll 2 rows per iter for MLP.
    #pragma unroll 1
    for (int t0 = tid; t0 < T_DIM; t0 += 2 * NTHREADS) {
        const int t1 = t0 + NTHREADS;

        float4 a0 = xp[t0 * 4 + 0];
        float4 a1 = xp[t0 * 4 + 1];
        float4 a2 = xp[t0 * 4 + 2];
        float4 a3 = xp[t0 * 4 + 3];
        float4 b0 = xp[t1 * 4 + 0];
        float4 b1 = xp[t1 * 4 + 1];
        float4 b2 = xp[t1 * 4 + 2];
        float4 b3 = xp[t1 * 4 + 3];

        float va[M_DIM] = { a0.x, a0.y, a0.z, a0.w,  a1.x, a1.y, a1.z, a1.w,
                            a2.x, a2.y, a2.z, a2.w,  a3.x, a3.y, a3.z, a3.w };
        float vb[M_DIM] = { b0.x, b0.y, b0.z, b0.w,  b1.x, b1.y, b1.z, b1.w,
                            b2.x, b2.y, b2.z, b2.w,  b3.x, b3.y, b3.z, b3.w };

        #pragma unroll
        for (int m = 0; m < M_DIM; m++) {
            acc[NPAIRS + m] += va[m] + vb[m];
            #pragma unroll
            for (int n = m; n < M_DIM; n++) {
                acc[tri_idx(m, n)] = fmaf(va[m], va[n],
                                      fmaf(vb[m], vb[n], acc[tri_idx(m, n)]));
            }
        }
    }

    // ---- Reduce 152 accumulators across the 256 threads ----
    // 1) warp butterfly reduce
    #pragma unroll 1
    for (int i = 0; i < NACC; i++) {
        float v = acc[i];
        #pragma unroll
        for (int o = 16; o > 0; o >>= 1)
            v += __shfl_xor_sync(0xFFFFFFFFu, v, o);
        acc[i] = v;
    }

    __shared__ float red[NTHREADS / 32][NACC];
    const int wid = tid >> 5;
    const int lid = tid & 31;
    if (lid == 0) {
        #pragma unroll 1
        for (int i = 0; i < NACC; i++) red[wid][i] = acc[i];
    }
    __syncthreads();

    __shared__ float tot[NACC];
    if (tid < NACC) {
        float v = 0.0f;
        #pragma unroll
        for (int w = 0; w < NTHREADS / 32; w++) v += red[w][tid];
        tot[tid] = v;
    }
    __syncthreads();

    // ---- Finalize: each thread writes one cov[m][n] ----
    {
        const int m = tid >> 4;
        const int n = tid & 15;
        const int mm = (m < n) ? m : n;
        const int nn = (m < n) ? n : m;
        const float S  = tot[tri_idx(mm, nn)];
        const float sm = tot[NPAIRS + m];
        const float sn = tot[NPAIRS + n];
        const float inv_T  = 1.0f / (float)T_DIM;
        const float inv_T1 = 1.0f / (float)(T_DIM - 1);
        out[(size_t)bc * 256 + tid] = (S - sm * sn * inv_T) * inv_T1;
    }
}

extern "C" void kernel_launch(void* const* d_in, const int* in_sizes, int n_in,
                              void* d_out, int out_size)
{
    const float* x = (const float*)d_in[0];
    float* out = (float*)d_out;
    cov_kernel<<<256, NTHREADS>>>(x, out);
}